// round 8
// baseline (speedup 1.0000x reference)
#include <cuda_runtime.h>
#include <math.h>

// Problem constants
#define BSZ   32768
#define HDIM  256
#define ADIM  4
#define INF_STEPS 10

// ---------------------------------------------------------------------------
// Device scratch (allocation-free rule: __device__ globals), 16B aligned
// ---------------------------------------------------------------------------
__device__ __align__(16) float g_cond1[BSZ * HDIM];
__device__ __align__(16) float g_cskip[BSZ * HDIM];
__device__ __align__(16) float g_h    [BSZ * HDIM];
__device__ __align__(16) float g_t    [BSZ * HDIM];
__device__ __align__(16) float g_skip [BSZ * HDIM];
__device__ __align__(16) float g_x    [BSZ * ADIM];
__device__ __align__(16) float g_noise[INF_STEPS * BSZ * ADIM];
__device__ __align__(16) float g_v1   [INF_STEPS * HDIM];
__device__ __align__(16) float g_vsk  [INF_STEPS * HDIM];

// ---------------------------------------------------------------------------
// threefry2x32 (exact JAX 20-round block)
// ---------------------------------------------------------------------------
__host__ __device__ __forceinline__
void threefry2x32(unsigned k0, unsigned k1, unsigned c0, unsigned c1,
                  unsigned& o0, unsigned& o1)
{
    unsigned ks0 = k0, ks1 = k1, ks2 = k0 ^ k1 ^ 0x1BD11BDAu;
    unsigned x0 = c0 + ks0, x1 = c1 + ks1;
#define TFR(r) { x0 += x1; x1 = (x1 << (r)) | (x1 >> (32 - (r))); x1 ^= x0; }
    TFR(13) TFR(15) TFR(26) TFR(6)   x0 += ks1; x1 += ks2 + 1u;
    TFR(17) TFR(29) TFR(16) TFR(24)  x0 += ks2; x1 += ks0 + 2u;
    TFR(13) TFR(15) TFR(26) TFR(6)   x0 += ks0; x1 += ks1 + 3u;
    TFR(17) TFR(29) TFR(16) TFR(24)  x0 += ks1; x1 += ks2 + 4u;
    TFR(13) TFR(15) TFR(26) TFR(6)   x0 += ks2; x1 += ks0 + 5u;
#undef TFR
    o0 = x0; o1 = x1;
}

// ---------------------------------------------------------------------------
// erfinv: XLA f32 polynomial (Giles), matching lax.erf_inv
// ---------------------------------------------------------------------------
__device__ __forceinline__ float erfinv_xla(float x)
{
    float w = -log1pf(-x * x);
    float p;
    if (w < 5.0f) {
        w -= 2.5f;
        p = 2.81022636e-08f;
        p = fmaf(p, w, 3.43273939e-07f);
        p = fmaf(p, w, -3.5233877e-06f);
        p = fmaf(p, w, -4.39150654e-06f);
        p = fmaf(p, w, 0.00021858087f);
        p = fmaf(p, w, -0.00125372503f);
        p = fmaf(p, w, -0.00417768164f);
        p = fmaf(p, w, 0.246640727f);
        p = fmaf(p, w, 1.50140941f);
    } else {
        w = sqrtf(w) - 3.0f;
        p = -0.000200214257f;
        p = fmaf(p, w, 0.000100950558f);
        p = fmaf(p, w, 0.00134934322f);
        p = fmaf(p, w, -0.00367342844f);
        p = fmaf(p, w, 0.00573950773f);
        p = fmaf(p, w, -0.0076224613f);
        p = fmaf(p, w, 0.00943887047f);
        p = fmaf(p, w, 1.00167406f);
        p = fmaf(p, w, 2.83297682f);
    }
    return p * x;
}

__device__ __forceinline__ float bits_to_normal(unsigned bits)
{
    float f = __uint_as_float((bits >> 9) | 0x3f800000u) - 1.0f;
    const float lo = -0.99999994f;
    float u = f * 2.0f + lo;
    u = fmaxf(lo, u);
    return 1.41421356237f * erfinv_xla(u);
}

// Partitionable threefry bits: bits[i] = o0 ^ o1, counter (0, i)
__global__ void rng_normal_kernel(float* out, int n, unsigned k0, unsigned k1)
{
    int i = blockIdx.x * blockDim.x + threadIdx.x;
    if (i >= n) return;
    unsigned o0, o1;
    threefry2x32(k0, k1, 0u, (unsigned)i, o0, o1);
    out[i] = bits_to_normal(o0 ^ o1);
}

// ---------------------------------------------------------------------------
// GELU (exact erf form)
// ---------------------------------------------------------------------------
__device__ __forceinline__ float gelu_f(float x)
{
    return 0.5f * x * (1.0f + erff(x * 0.70710678118654752f));
}

// ---------------------------------------------------------------------------
// Timestep embedding projections for all 10 steps (tiny kernel).
// ---------------------------------------------------------------------------
__global__ void temb_kernel(const float* __restrict__ time_w,
                            const float* __restrict__ time_b,
                            const float* __restrict__ blk0_w1,
                            const float* __restrict__ blk0_skip_w)
{
    __shared__ float se[HDIM];
    __shared__ float temb[HDIM];
    int s = blockIdx.x;
    double t = (double)(90 - 10 * s);
    int j = threadIdx.x;

    const double cfreq = -9.210340371976184 / 127.0;
    if (j < 128) {
        double fr = exp((double)j * cfreq);
        se[j] = (float)sin(t * fr);
    } else {
        double fr = exp((double)(j - 128) * cfreq);
        se[j] = (float)cos(t * fr);
    }
    __syncthreads();

    float acc = time_b[j];
    #pragma unroll 8
    for (int k = 0; k < HDIM; k++) acc = fmaf(se[k], time_w[k * HDIM + j], acc);
    temb[j] = gelu_f(acc);
    __syncthreads();

    float a1 = 0.0f, as = 0.0f;
    #pragma unroll 8
    for (int k = 0; k < HDIM; k++) {
        float tv = temb[k];
        a1 = fmaf(tv, blk0_w1    [(256 + k) * HDIM + j], a1);
        as = fmaf(tv, blk0_skip_w[(256 + k) * HDIM + j], as);
    }
    g_v1 [s * HDIM + j] = a1;
    g_vsk[s * HDIM + j] = as;
}

// ---------------------------------------------------------------------------
// Build h1 = gelu(cond1 + v1 + x @ W1x) -> g_t ; skip = cskip + vsk + x @ Wsx
// ---------------------------------------------------------------------------
__global__ void build_kernel(const float* __restrict__ blk0_w1,
                             const float* __restrict__ blk0_skip_w,
                             int step)
{
    int idx = blockIdx.x * 256 + threadIdx.x;
    int n = idx & 255;
    int m = idx >> 8;

    float x0 = g_x[m * 4 + 0], x1 = g_x[m * 4 + 1];
    float x2 = g_x[m * 4 + 2], x3 = g_x[m * 4 + 3];

    float h1 = g_cond1[idx] + g_v1[step * HDIM + n];
    h1 = fmaf(x0, blk0_w1[512 * HDIM + n], h1);
    h1 = fmaf(x1, blk0_w1[513 * HDIM + n], h1);
    h1 = fmaf(x2, blk0_w1[514 * HDIM + n], h1);
    h1 = fmaf(x3, blk0_w1[515 * HDIM + n], h1);
    g_t[idx] = gelu_f(h1);

    float sk = g_cskip[idx] + g_vsk[step * HDIM + n];
    sk = fmaf(x0, blk0_skip_w[512 * HDIM + n], sk);
    sk = fmaf(x1, blk0_skip_w[513 * HDIM + n], sk);
    sk = fmaf(x2, blk0_skip_w[514 * HDIM + n], sk);
    sk = fmaf(x3, blk0_skip_w[515 * HDIM + n], sk);
    g_skip[idx] = sk;
}

// ---------------------------------------------------------------------------
// Double-buffered packed-f32x2 SGEMM:
//   C[M,256] = A[M,256] @ W[256,256] (+bias)(gelu)(+R)
// Tiles 128x128x16, 256 threads, 8x8 microtiles, 2 CTAs/SM.
// Steady state: next tile's LDGs issued before compute (latency hidden),
// one __syncthreads per k-tile.
// ---------------------------------------------------------------------------
__device__ __forceinline__ unsigned long long pack2(float lo, float hi)
{
    unsigned long long r;
    asm("mov.b64 %0, {%1, %2};" : "=l"(r) : "f"(lo), "f"(hi));
    return r;
}
__device__ __forceinline__ void unpack2(unsigned long long v, float& lo, float& hi)
{
    asm("mov.b64 {%0, %1}, %2;" : "=f"(lo), "=f"(hi) : "l"(v));
}
__device__ __forceinline__ unsigned long long ffma2(unsigned long long a,
                                                    unsigned long long b,
                                                    unsigned long long c)
{
    unsigned long long d;
    asm("fma.rn.f32x2 %0, %1, %2, %3;" : "=l"(d) : "l"(a), "l"(b), "l"(c));
    return d;
}

#define GBM 128
#define GBN 128
#define GBK 16
#define KTILES (256 / GBK)

template <int EPI>
__global__ __launch_bounds__(256, 2)
void sgemm_kernel(const float* __restrict__ A, const float* __restrict__ W,
                  const float* __restrict__ bias, const float* R, float* C)
{
    __shared__ float As[2][GBK][GBM + 4];   // [buf][k][m]
    __shared__ float Bs[2][GBK][GBN];       // [buf][k][n]

    const int K = 256, N = 256;
    int tid = threadIdx.x;
    int tx = tid & 15, ty = tid >> 4;
    int m0 = blockIdx.y * GBM;
    int n0 = blockIdx.x * GBN;

    // Per-thread load coordinates (2 chunks each for A and B)
    int a_m0 = tid >> 2,           a_kq0 = tid & 3;
    int a_m1 = (tid + 256) >> 2,   a_kq1 = (tid + 256) & 3;
    int b_kr0 = tid >> 5,          b_nq0 = tid & 31;
    int b_kr1 = (tid + 256) >> 5,  b_nq1 = (tid + 256) & 31;

    const float* Ap0 = A + (size_t)(m0 + a_m0) * K + a_kq0 * 4;
    const float* Ap1 = A + (size_t)(m0 + a_m1) * K + a_kq1 * 4;
    const float* Bp0 = W + (size_t)b_kr0 * N + n0 + b_nq0 * 4;
    const float* Bp1 = W + (size_t)b_kr1 * N + n0 + b_nq1 * 4;

    // Prologue: tile 0 -> buffer 0
    {
        float4 a0 = *(const float4*)Ap0;
        float4 a1 = *(const float4*)Ap1;
        float4 bz0 = *(const float4*)Bp0;
        float4 bz1 = *(const float4*)Bp1;
        As[0][a_kq0 * 4 + 0][a_m0] = a0.x;
        As[0][a_kq0 * 4 + 1][a_m0] = a0.y;
        As[0][a_kq0 * 4 + 2][a_m0] = a0.z;
        As[0][a_kq0 * 4 + 3][a_m0] = a0.w;
        As[0][a_kq1 * 4 + 0][a_m1] = a1.x;
        As[0][a_kq1 * 4 + 1][a_m1] = a1.y;
        As[0][a_kq1 * 4 + 2][a_m1] = a1.z;
        As[0][a_kq1 * 4 + 3][a_m1] = a1.w;
        *(float4*)&Bs[0][b_kr0][b_nq0 * 4] = bz0;
        *(float4*)&Bs[0][b_kr1][b_nq1 * 4] = bz1;
    }
    __syncthreads();

    unsigned long long acc[8][4];
    #pragma unroll
    for (int i = 0; i < 8; i++)
        #pragma unroll
        for (int j = 0; j < 4; j++) acc[i][j] = 0ull;

    for (int kt = 0; kt < KTILES; kt++) {
        int cur = kt & 1;
        float4 pa0, pa1, pb0, pb1;
        if (kt < KTILES - 1) {
            int k0 = (kt + 1) * GBK;
            pa0 = *(const float4*)(Ap0 + k0);
            pa1 = *(const float4*)(Ap1 + k0);
            pb0 = *(const float4*)(Bp0 + (size_t)k0 * N);
            pb1 = *(const float4*)(Bp1 + (size_t)k0 * N);
        }

        #pragma unroll
        for (int k = 0; k < GBK; k++) {
            float4 a0 = *(const float4*)&As[cur][k][ty * 8];
            float4 a1 = *(const float4*)&As[cur][k][ty * 8 + 4];
            float4 b0 = *(const float4*)&Bs[cur][k][tx * 8];
            float4 b1 = *(const float4*)&Bs[cur][k][tx * 8 + 4];
            unsigned long long bp[4] = { pack2(b0.x, b0.y), pack2(b0.z, b0.w),
                                         pack2(b1.x, b1.y), pack2(b1.z, b1.w) };
            float av[8] = { a0.x, a0.y, a0.z, a0.w, a1.x, a1.y, a1.z, a1.w };
            #pragma unroll
            for (int i = 0; i < 8; i++) {
                unsigned long long ap = pack2(av[i], av[i]);
                #pragma unroll
                for (int j = 0; j < 4; j++)
                    acc[i][j] = ffma2(ap, bp[j], acc[i][j]);
            }
        }

        if (kt < KTILES - 1) {
            int nxt = cur ^ 1;
            As[nxt][a_kq0 * 4 + 0][a_m0] = pa0.x;
            As[nxt][a_kq0 * 4 + 1][a_m0] = pa0.y;
            As[nxt][a_kq0 * 4 + 2][a_m0] = pa0.z;
            As[nxt][a_kq0 * 4 + 3][a_m0] = pa0.w;
            As[nxt][a_kq1 * 4 + 0][a_m1] = pa1.x;
            As[nxt][a_kq1 * 4 + 1][a_m1] = pa1.y;
            As[nxt][a_kq1 * 4 + 2][a_m1] = pa1.z;
            As[nxt][a_kq1 * 4 + 3][a_m1] = pa1.w;
            *(float4*)&Bs[nxt][b_kr0][b_nq0 * 4] = pb0;
            *(float4*)&Bs[nxt][b_kr1][b_nq1 * 4] = pb1;
            __syncthreads();
        }
    }

    // Epilogue
    float bb[8];
    #pragma unroll
    for (int j = 0; j < 8; j++)
        bb[j] = (EPI & 1) ? bias[n0 + tx * 8 + j] : 0.0f;

    #pragma unroll
    for (int i = 0; i < 8; i++) {
        int m = m0 + ty * 8 + i;
        float cv[8];
        #pragma unroll
        for (int j = 0; j < 4; j++) unpack2(acc[i][j], cv[2 * j], cv[2 * j + 1]);
        #pragma unroll
        for (int j = 0; j < 8; j++) {
            float c = cv[j] + bb[j];
            if (EPI & 2) c = gelu_f(c);
            cv[j] = c;
        }
        if (EPI & 4) {
            float4 r0 = *(const float4*)&R[(size_t)m * N + n0 + tx * 8];
            float4 r1 = *(const float4*)&R[(size_t)m * N + n0 + tx * 8 + 4];
            cv[0] += r0.x; cv[1] += r0.y; cv[2] += r0.z; cv[3] += r0.w;
            cv[4] += r1.x; cv[5] += r1.y; cv[6] += r1.z; cv[7] += r1.w;
        }
        float4 o0 = make_float4(cv[0], cv[1], cv[2], cv[3]);
        float4 o1 = make_float4(cv[4], cv[5], cv[6], cv[7]);
        *(float4*)&C[(size_t)m * N + n0 + tx * 8]     = o0;
        *(float4*)&C[(size_t)m * N + n0 + tx * 8 + 4] = o1;
    }
}

// ---------------------------------------------------------------------------
// pred = h @ final_w + final_b ; diffusion x-update (+ optional clip to out)
// ---------------------------------------------------------------------------
__global__ void final_update_kernel(const float* __restrict__ fw,
                                    const float* __restrict__ fb,
                                    int step, float c1, float sqrt_a,
                                    float sqrt_b, int add_noise, float* out)
{
    __shared__ float sfw[HDIM * ADIM];
    int tid = threadIdx.x;
    #pragma unroll
    for (int l = 0; l < 4; l++) sfw[tid + l * 256] = fw[tid + l * 256];
    __syncthreads();

    int m = blockIdx.x * 64 + (tid >> 2);
    int a = tid & 3;

    const float4* h4 = (const float4*)&g_h[(size_t)m * HDIM];
    float acc = 0.0f;
    #pragma unroll 8
    for (int k4 = 0; k4 < HDIM / 4; k4++) {
        float4 hv = h4[k4];
        acc = fmaf(hv.x, sfw[(k4 * 4 + 0) * 4 + a], acc);
        acc = fmaf(hv.y, sfw[(k4 * 4 + 1) * 4 + a], acc);
        acc = fmaf(hv.z, sfw[(k4 * 4 + 2) * 4 + a], acc);
        acc = fmaf(hv.w, sfw[(k4 * 4 + 3) * 4 + a], acc);
    }
    float pred = acc + fb[a];

    float x = g_x[m * 4 + a];
    x = (x - c1 * pred) / sqrt_a;
    if (add_noise)
        x += sqrt_b * g_noise[((size_t)step * BSZ + m) * 4 + a];
    g_x[m * 4 + a] = x;
    if (out) out[m * 4 + a] = fminf(1.0f, fmaxf(-1.0f, x));
}

// ---------------------------------------------------------------------------
// Launch
// ---------------------------------------------------------------------------
extern "C" void kernel_launch(void* const* d_in, const int* in_sizes, int n_in,
                              void* d_out, int out_size)
{
    (void)n_in; (void)out_size;

    const float *features, *cond_w, *cond_b, *time_w, *time_b;
    const float *blk0_w1, *blk0_b1, *blk0_w2, *blk0_b2, *blk0_skip_w, *blk0_skip_b;
    const float *blks_w1, *blks_b1, *blks_w2, *blks_b2, *final_w, *final_b;

    if (in_sizes[0] == BSZ * HDIM) {
        features    = (const float*)d_in[0];
        cond_w      = (const float*)d_in[1];
        cond_b      = (const float*)d_in[2];
        time_w      = (const float*)d_in[3];
        time_b      = (const float*)d_in[4];
        blk0_w1     = (const float*)d_in[5];
        blk0_b1     = (const float*)d_in[6];
        blk0_w2     = (const float*)d_in[7];
        blk0_b2     = (const float*)d_in[8];
        blk0_skip_w = (const float*)d_in[9];
        blk0_skip_b = (const float*)d_in[10];
        blks_w1     = (const float*)d_in[11];
        blks_b1     = (const float*)d_in[12];
        blks_w2     = (const float*)d_in[13];
        blks_b2     = (const float*)d_in[14];
        final_w     = (const float*)d_in[15];
        final_b     = (const float*)d_in[16];
    } else {
        blk0_b1     = (const float*)d_in[0];
        blk0_b2     = (const float*)d_in[1];
        blk0_skip_b = (const float*)d_in[2];
        blk0_skip_w = (const float*)d_in[3];
        blk0_w1     = (const float*)d_in[4];
        blk0_w2     = (const float*)d_in[5];
        blks_b1     = (const float*)d_in[6];
        blks_b2     = (const float*)d_in[7];
        blks_w1     = (const float*)d_in[8];
        blks_w2     = (const float*)d_in[9];
        cond_b      = (const float*)d_in[10];
        cond_w      = (const float*)d_in[11];
        features    = (const float*)d_in[12];
        final_b     = (const float*)d_in[13];
        final_w     = (const float*)d_in[14];
        time_b      = (const float*)d_in[15];
        time_w      = (const float*)d_in[16];
    }

    float *p_cond1, *p_cskip, *p_h, *p_t, *p_skip, *p_x, *p_noise;
    cudaGetSymbolAddress((void**)&p_cond1, g_cond1);
    cudaGetSymbolAddress((void**)&p_cskip, g_cskip);
    cudaGetSymbolAddress((void**)&p_h,     g_h);
    cudaGetSymbolAddress((void**)&p_t,     g_t);
    cudaGetSymbolAddress((void**)&p_skip,  g_skip);
    cudaGetSymbolAddress((void**)&p_x,     g_x);
    cudaGetSymbolAddress((void**)&p_noise, g_noise);

    // betas / alphas_cumprod (fp32 sequential cumprod, matching jnp)
    float betas[100], acps[100];
    float cp = 1.0f;
    for (int i = 0; i < 100; i++) {
        betas[i] = (float)(1e-4 + (0.02 - 1e-4) * ((double)i / 99.0));
        cp *= (1.0f - betas[i]);
        acps[i] = cp;
    }

    // PRNG keys: key(42) = [0,42]; fold_in(key,d) = threefry(key; 0, d)
    unsigned kx0, kx1, kn0, kn1;
    threefry2x32(0u, 42u, 0u, 999u, kx0, kx1);
    threefry2x32(0u, 42u, 0u, 7u,   kn0, kn1);

    rng_normal_kernel<<<512, 256>>>(p_x, BSZ * ADIM, kx0, kx1);
    rng_normal_kernel<<<5120, 256>>>(p_noise, INF_STEPS * BSZ * ADIM, kn0, kn1);

    temb_kernel<<<INF_STEPS, 256>>>(time_w, time_b, blk0_w1, blk0_skip_w);

    dim3 ggrid(2, BSZ / GBM);

    sgemm_kernel<1><<<ggrid, 256>>>(features, cond_w, cond_b, nullptr, p_h);
    sgemm_kernel<1><<<ggrid, 256>>>(p_h, blk0_w1, blk0_b1, nullptr, p_cond1);
    sgemm_kernel<1><<<ggrid, 256>>>(p_h, blk0_skip_w, blk0_skip_b, nullptr, p_cskip);

    for (int s = 0; s < INF_STEPS; s++) {
        int t = 90 - 10 * s;
        float b   = betas[t];
        float a   = 1.0f - b;
        float acp = acps[t];
        float c1  = b / sqrtf(1.0f - acp);
        float sa  = sqrtf(a);
        float sb  = sqrtf(b);

        build_kernel<<<BSZ, 256>>>(blk0_w1, blk0_skip_w, s);

        sgemm_kernel<7><<<ggrid, 256>>>(p_t, blk0_w2, blk0_b2, p_skip, p_h);

        for (int i = 0; i < 3; i++) {
            sgemm_kernel<3><<<ggrid, 256>>>(p_h, blks_w1 + i * 65536,
                                            blks_b1 + i * 256, nullptr, p_t);
            sgemm_kernel<7><<<ggrid, 256>>>(p_t, blks_w2 + i * 65536,
                                            blks_b2 + i * 256, p_h, p_h);
        }

        final_update_kernel<<<BSZ / 64, 256>>>(final_w, final_b, s, c1, sa, sb,
                                               (t > 0) ? 1 : 0,
                                               (s == INF_STEPS - 1) ? (float*)d_out
                                                                    : nullptr);
    }
}

// round 9
// speedup vs baseline: 1.0525x; 1.0525x over previous
#include <cuda_runtime.h>
#include <math.h>

// Problem constants
#define BSZ   32768
#define HDIM  256
#define ADIM  4
#define INF_STEPS 10

// ---------------------------------------------------------------------------
// Device scratch (allocation-free rule: __device__ globals), 16B aligned
// ---------------------------------------------------------------------------
__device__ __align__(16) float g_cond1[BSZ * HDIM];
__device__ __align__(16) float g_cskip[BSZ * HDIM];
__device__ __align__(16) float g_h    [BSZ * HDIM];
__device__ __align__(16) float g_t    [BSZ * HDIM];
__device__ __align__(16) float g_skip [BSZ * HDIM];
__device__ __align__(16) float g_x    [BSZ * ADIM];
__device__ __align__(16) float g_noise[INF_STEPS * BSZ * ADIM];
__device__ __align__(16) float g_v1   [INF_STEPS * HDIM];
__device__ __align__(16) float g_vsk  [INF_STEPS * HDIM];

// ---------------------------------------------------------------------------
// threefry2x32 (exact JAX 20-round block)
// ---------------------------------------------------------------------------
__host__ __device__ __forceinline__
void threefry2x32(unsigned k0, unsigned k1, unsigned c0, unsigned c1,
                  unsigned& o0, unsigned& o1)
{
    unsigned ks0 = k0, ks1 = k1, ks2 = k0 ^ k1 ^ 0x1BD11BDAu;
    unsigned x0 = c0 + ks0, x1 = c1 + ks1;
#define TFR(r) { x0 += x1; x1 = (x1 << (r)) | (x1 >> (32 - (r))); x1 ^= x0; }
    TFR(13) TFR(15) TFR(26) TFR(6)   x0 += ks1; x1 += ks2 + 1u;
    TFR(17) TFR(29) TFR(16) TFR(24)  x0 += ks2; x1 += ks0 + 2u;
    TFR(13) TFR(15) TFR(26) TFR(6)   x0 += ks0; x1 += ks1 + 3u;
    TFR(17) TFR(29) TFR(16) TFR(24)  x0 += ks1; x1 += ks2 + 4u;
    TFR(13) TFR(15) TFR(26) TFR(6)   x0 += ks2; x1 += ks0 + 5u;
#undef TFR
    o0 = x0; o1 = x1;
}

// ---------------------------------------------------------------------------
// erfinv: XLA f32 polynomial (Giles), matching lax.erf_inv
// ---------------------------------------------------------------------------
__device__ __forceinline__ float erfinv_xla(float x)
{
    float w = -log1pf(-x * x);
    float p;
    if (w < 5.0f) {
        w -= 2.5f;
        p = 2.81022636e-08f;
        p = fmaf(p, w, 3.43273939e-07f);
        p = fmaf(p, w, -3.5233877e-06f);
        p = fmaf(p, w, -4.39150654e-06f);
        p = fmaf(p, w, 0.00021858087f);
        p = fmaf(p, w, -0.00125372503f);
        p = fmaf(p, w, -0.00417768164f);
        p = fmaf(p, w, 0.246640727f);
        p = fmaf(p, w, 1.50140941f);
    } else {
        w = sqrtf(w) - 3.0f;
        p = -0.000200214257f;
        p = fmaf(p, w, 0.000100950558f);
        p = fmaf(p, w, 0.00134934322f);
        p = fmaf(p, w, -0.00367342844f);
        p = fmaf(p, w, 0.00573950773f);
        p = fmaf(p, w, -0.0076224613f);
        p = fmaf(p, w, 0.00943887047f);
        p = fmaf(p, w, 1.00167406f);
        p = fmaf(p, w, 2.83297682f);
    }
    return p * x;
}

__device__ __forceinline__ float bits_to_normal(unsigned bits)
{
    float f = __uint_as_float((bits >> 9) | 0x3f800000u) - 1.0f;
    const float lo = -0.99999994f;
    float u = f * 2.0f + lo;
    u = fmaxf(lo, u);
    return 1.41421356237f * erfinv_xla(u);
}

// Partitionable threefry bits: bits[i] = o0 ^ o1, counter (0, i)
__global__ void rng_normal_kernel(float* out, int n, unsigned k0, unsigned k1)
{
    int i = blockIdx.x * blockDim.x + threadIdx.x;
    if (i >= n) return;
    unsigned o0, o1;
    threefry2x32(k0, k1, 0u, (unsigned)i, o0, o1);
    out[i] = bits_to_normal(o0 ^ o1);
}

// ---------------------------------------------------------------------------
// GELU (exact erf form)
// ---------------------------------------------------------------------------
__device__ __forceinline__ float gelu_f(float x)
{
    return 0.5f * x * (1.0f + erff(x * 0.70710678118654752f));
}

// ---------------------------------------------------------------------------
// Timestep embedding projections for all 10 steps (tiny kernel).
// ---------------------------------------------------------------------------
__global__ void temb_kernel(const float* __restrict__ time_w,
                            const float* __restrict__ time_b,
                            const float* __restrict__ blk0_w1,
                            const float* __restrict__ blk0_skip_w)
{
    __shared__ float se[HDIM];
    __shared__ float temb[HDIM];
    int s = blockIdx.x;
    double t = (double)(90 - 10 * s);
    int j = threadIdx.x;

    const double cfreq = -9.210340371976184 / 127.0;
    if (j < 128) {
        double fr = exp((double)j * cfreq);
        se[j] = (float)sin(t * fr);
    } else {
        double fr = exp((double)(j - 128) * cfreq);
        se[j] = (float)cos(t * fr);
    }
    __syncthreads();

    float acc = time_b[j];
    #pragma unroll 8
    for (int k = 0; k < HDIM; k++) acc = fmaf(se[k], time_w[k * HDIM + j], acc);
    temb[j] = gelu_f(acc);
    __syncthreads();

    float a1 = 0.0f, as = 0.0f;
    #pragma unroll 8
    for (int k = 0; k < HDIM; k++) {
        float tv = temb[k];
        a1 = fmaf(tv, blk0_w1    [(256 + k) * HDIM + j], a1);
        as = fmaf(tv, blk0_skip_w[(256 + k) * HDIM + j], as);
    }
    g_v1 [s * HDIM + j] = a1;
    g_vsk[s * HDIM + j] = as;
}

// ---------------------------------------------------------------------------
// Build h1 = gelu(cond1 + v1 + x @ W1x) -> g_t ; skip = cskip + vsk + x @ Wsx
// ---------------------------------------------------------------------------
__global__ void build_kernel(const float* __restrict__ blk0_w1,
                             const float* __restrict__ blk0_skip_w,
                             int step)
{
    int idx = blockIdx.x * 256 + threadIdx.x;
    int n = idx & 255;
    int m = idx >> 8;

    float x0 = g_x[m * 4 + 0], x1 = g_x[m * 4 + 1];
    float x2 = g_x[m * 4 + 2], x3 = g_x[m * 4 + 3];

    float h1 = g_cond1[idx] + g_v1[step * HDIM + n];
    h1 = fmaf(x0, blk0_w1[512 * HDIM + n], h1);
    h1 = fmaf(x1, blk0_w1[513 * HDIM + n], h1);
    h1 = fmaf(x2, blk0_w1[514 * HDIM + n], h1);
    h1 = fmaf(x3, blk0_w1[515 * HDIM + n], h1);
    g_t[idx] = gelu_f(h1);

    float sk = g_cskip[idx] + g_vsk[step * HDIM + n];
    sk = fmaf(x0, blk0_skip_w[512 * HDIM + n], sk);
    sk = fmaf(x1, blk0_skip_w[513 * HDIM + n], sk);
    sk = fmaf(x2, blk0_skip_w[514 * HDIM + n], sk);
    sk = fmaf(x3, blk0_skip_w[515 * HDIM + n], sk);
    g_skip[idx] = sk;
}

// ---------------------------------------------------------------------------
// Double-buffered packed-f32x2 SGEMM:
//   C[M,256] = A[M,256] @ W[256,256] (+bias)(gelu)(+R)
// Tiles 128x128x16, 256 threads, 8x8 microtiles, 2 CTAs/SM.
// Steady state: next tile's LDGs issued before compute (latency hidden),
// one __syncthreads per k-tile.
// ---------------------------------------------------------------------------
__device__ __forceinline__ unsigned long long pack2(float lo, float hi)
{
    unsigned long long r;
    asm("mov.b64 %0, {%1, %2};" : "=l"(r) : "f"(lo), "f"(hi));
    return r;
}
__device__ __forceinline__ void unpack2(unsigned long long v, float& lo, float& hi)
{
    asm("mov.b64 {%0, %1}, %2;" : "=f"(lo), "=f"(hi) : "l"(v));
}
__device__ __forceinline__ unsigned long long ffma2(unsigned long long a,
                                                    unsigned long long b,
                                                    unsigned long long c)
{
    unsigned long long d;
    asm("fma.rn.f32x2 %0, %1, %2, %3;" : "=l"(d) : "l"(a), "l"(b), "l"(c));
    return d;
}

#define GBM 128
#define GBN 128
#define GBK 16
#define KTILES (256 / GBK)

template <int EPI>
__global__ __launch_bounds__(256, 2)
void sgemm_kernel(const float* __restrict__ A, const float* __restrict__ W,
                  const float* __restrict__ bias, const float* R, float* C)
{
    __shared__ float As[2][GBK][GBM + 4];   // [buf][k][m]
    __shared__ float Bs[2][GBK][GBN];       // [buf][k][n]

    const int K = 256, N = 256;
    int tid = threadIdx.x;
    int tx = tid & 15, ty = tid >> 4;
    int m0 = blockIdx.y * GBM;
    int n0 = blockIdx.x * GBN;

    // Per-thread load coordinates (2 chunks each for A and B)
    int a_m0 = tid >> 2,           a_kq0 = tid & 3;
    int a_m1 = (tid + 256) >> 2,   a_kq1 = (tid + 256) & 3;
    int b_kr0 = tid >> 5,          b_nq0 = tid & 31;
    int b_kr1 = (tid + 256) >> 5,  b_nq1 = (tid + 256) & 31;

    const float* Ap0 = A + (size_t)(m0 + a_m0) * K + a_kq0 * 4;
    const float* Ap1 = A + (size_t)(m0 + a_m1) * K + a_kq1 * 4;
    const float* Bp0 = W + (size_t)b_kr0 * N + n0 + b_nq0 * 4;
    const float* Bp1 = W + (size_t)b_kr1 * N + n0 + b_nq1 * 4;

    // Prologue: tile 0 -> buffer 0
    {
        float4 a0 = *(const float4*)Ap0;
        float4 a1 = *(const float4*)Ap1;
        float4 bz0 = *(const float4*)Bp0;
        float4 bz1 = *(const float4*)Bp1;
        As[0][a_kq0 * 4 + 0][a_m0] = a0.x;
        As[0][a_kq0 * 4 + 1][a_m0] = a0.y;
        As[0][a_kq0 * 4 + 2][a_m0] = a0.z;
        As[0][a_kq0 * 4 + 3][a_m0] = a0.w;
        As[0][a_kq1 * 4 + 0][a_m1] = a1.x;
        As[0][a_kq1 * 4 + 1][a_m1] = a1.y;
        As[0][a_kq1 * 4 + 2][a_m1] = a1.z;
        As[0][a_kq1 * 4 + 3][a_m1] = a1.w;
        *(float4*)&Bs[0][b_kr0][b_nq0 * 4] = bz0;
        *(float4*)&Bs[0][b_kr1][b_nq1 * 4] = bz1;
    }
    __syncthreads();

    unsigned long long acc[8][4];
    #pragma unroll
    for (int i = 0; i < 8; i++)
        #pragma unroll
        for (int j = 0; j < 4; j++) acc[i][j] = 0ull;

    for (int kt = 0; kt < KTILES; kt++) {
        int cur = kt & 1;
        float4 pa0, pa1, pb0, pb1;
        if (kt < KTILES - 1) {
            int k0 = (kt + 1) * GBK;
            pa0 = *(const float4*)(Ap0 + k0);
            pa1 = *(const float4*)(Ap1 + k0);
            pb0 = *(const float4*)(Bp0 + (size_t)k0 * N);
            pb1 = *(const float4*)(Bp1 + (size_t)k0 * N);
        }

        #pragma unroll
        for (int k = 0; k < GBK; k++) {
            float4 a0 = *(const float4*)&As[cur][k][ty * 8];
            float4 a1 = *(const float4*)&As[cur][k][ty * 8 + 4];
            float4 b0 = *(const float4*)&Bs[cur][k][tx * 8];
            float4 b1 = *(const float4*)&Bs[cur][k][tx * 8 + 4];
            unsigned long long bp[4] = { pack2(b0.x, b0.y), pack2(b0.z, b0.w),
                                         pack2(b1.x, b1.y), pack2(b1.z, b1.w) };
            float av[8] = { a0.x, a0.y, a0.z, a0.w, a1.x, a1.y, a1.z, a1.w };
            #pragma unroll
            for (int i = 0; i < 8; i++) {
                unsigned long long ap = pack2(av[i], av[i]);
                #pragma unroll
                for (int j = 0; j < 4; j++)
                    acc[i][j] = ffma2(ap, bp[j], acc[i][j]);
            }
        }

        if (kt < KTILES - 1) {
            int nxt = cur ^ 1;
            As[nxt][a_kq0 * 4 + 0][a_m0] = pa0.x;
            As[nxt][a_kq0 * 4 + 1][a_m0] = pa0.y;
            As[nxt][a_kq0 * 4 + 2][a_m0] = pa0.z;
            As[nxt][a_kq0 * 4 + 3][a_m0] = pa0.w;
            As[nxt][a_kq1 * 4 + 0][a_m1] = pa1.x;
            As[nxt][a_kq1 * 4 + 1][a_m1] = pa1.y;
            As[nxt][a_kq1 * 4 + 2][a_m1] = pa1.z;
            As[nxt][a_kq1 * 4 + 3][a_m1] = pa1.w;
            *(float4*)&Bs[nxt][b_kr0][b_nq0 * 4] = pb0;
            *(float4*)&Bs[nxt][b_kr1][b_nq1 * 4] = pb1;
            __syncthreads();
        }
    }

    // Epilogue
    float bb[8];
    #pragma unroll
    for (int j = 0; j < 8; j++)
        bb[j] = (EPI & 1) ? bias[n0 + tx * 8 + j] : 0.0f;

    #pragma unroll
    for (int i = 0; i < 8; i++) {
        int m = m0 + ty * 8 + i;
        float cv[8];
        #pragma unroll
        for (int j = 0; j < 4; j++) unpack2(acc[i][j], cv[2 * j], cv[2 * j + 1]);
        #pragma unroll
        for (int j = 0; j < 8; j++) {
            float c = cv[j] + bb[j];
            if (EPI & 2) c = gelu_f(c);
            cv[j] = c;
        }
        if (EPI & 4) {
            float4 r0 = *(const float4*)&R[(size_t)m * N + n0 + tx * 8];
            float4 r1 = *(const float4*)&R[(size_t)m * N + n0 + tx * 8 + 4];
            cv[0] += r0.x; cv[1] += r0.y; cv[2] += r0.z; cv[3] += r0.w;
            cv[4] += r1.x; cv[5] += r1.y; cv[6] += r1.z; cv[7] += r1.w;
        }
        float4 o0 = make_float4(cv[0], cv[1], cv[2], cv[3]);
        float4 o1 = make_float4(cv[4], cv[5], cv[6], cv[7]);
        *(float4*)&C[(size_t)m * N + n0 + tx * 8]     = o0;
        *(float4*)&C[(size_t)m * N + n0 + tx * 8 + 4] = o1;
    }
}

// ---------------------------------------------------------------------------
// pred = h @ final_w + final_b ; diffusion x-update (+ optional clip to out)
// ---------------------------------------------------------------------------
__global__ void final_update_kernel(const float* __restrict__ fw,
                                    const float* __restrict__ fb,
                                    int step, float c1, float sqrt_a,
                                    float sqrt_b, int add_noise, float* out)
{
    __shared__ float sfw[HDIM * ADIM];
    int tid = threadIdx.x;
    #pragma unroll
    for (int l = 0; l < 4; l++) sfw[tid + l * 256] = fw[tid + l * 256];
    __syncthreads();

    int m = blockIdx.x * 64 + (tid >> 2);
    int a = tid & 3;

    const float4* h4 = (const float4*)&g_h[(size_t)m * HDIM];
    float acc = 0.0f;
    #pragma unroll 8
    for (int k4 = 0; k4 < HDIM / 4; k4++) {
        float4 hv = h4[k4];
        acc = fmaf(hv.x, sfw[(k4 * 4 + 0) * 4 + a], acc);
        acc = fmaf(hv.y, sfw[(k4 * 4 + 1) * 4 + a], acc);
        acc = fmaf(hv.z, sfw[(k4 * 4 + 2) * 4 + a], acc);
        acc = fmaf(hv.w, sfw[(k4 * 4 + 3) * 4 + a], acc);
    }
    float pred = acc + fb[a];

    float x = g_x[m * 4 + a];
    x = (x - c1 * pred) / sqrt_a;
    if (add_noise)
        x += sqrt_b * g_noise[((size_t)step * BSZ + m) * 4 + a];
    g_x[m * 4 + a] = x;
    if (out) out[m * 4 + a] = fminf(1.0f, fmaxf(-1.0f, x));
}

// ---------------------------------------------------------------------------
// Launch
// ---------------------------------------------------------------------------
extern "C" void kernel_launch(void* const* d_in, const int* in_sizes, int n_in,
                              void* d_out, int out_size)
{
    (void)n_in; (void)out_size;

    const float *features, *cond_w, *cond_b, *time_w, *time_b;
    const float *blk0_w1, *blk0_b1, *blk0_w2, *blk0_b2, *blk0_skip_w, *blk0_skip_b;
    const float *blks_w1, *blks_b1, *blks_w2, *blks_b2, *final_w, *final_b;

    if (in_sizes[0] == BSZ * HDIM) {
        features    = (const float*)d_in[0];
        cond_w      = (const float*)d_in[1];
        cond_b      = (const float*)d_in[2];
        time_w      = (const float*)d_in[3];
        time_b      = (const float*)d_in[4];
        blk0_w1     = (const float*)d_in[5];
        blk0_b1     = (const float*)d_in[6];
        blk0_w2     = (const float*)d_in[7];
        blk0_b2     = (const float*)d_in[8];
        blk0_skip_w = (const float*)d_in[9];
        blk0_skip_b = (const float*)d_in[10];
        blks_w1     = (const float*)d_in[11];
        blks_b1     = (const float*)d_in[12];
        blks_w2     = (const float*)d_in[13];
        blks_b2     = (const float*)d_in[14];
        final_w     = (const float*)d_in[15];
        final_b     = (const float*)d_in[16];
    } else {
        blk0_b1     = (const float*)d_in[0];
        blk0_b2     = (const float*)d_in[1];
        blk0_skip_b = (const float*)d_in[2];
        blk0_skip_w = (const float*)d_in[3];
        blk0_w1     = (const float*)d_in[4];
        blk0_w2     = (const float*)d_in[5];
        blks_b1     = (const float*)d_in[6];
        blks_b2     = (const float*)d_in[7];
        blks_w1     = (const float*)d_in[8];
        blks_w2     = (const float*)d_in[9];
        cond_b      = (const float*)d_in[10];
        cond_w      = (const float*)d_in[11];
        features    = (const float*)d_in[12];
        final_b     = (const float*)d_in[13];
        final_w     = (const float*)d_in[14];
        time_b      = (const float*)d_in[15];
        time_w      = (const float*)d_in[16];
    }

    float *p_cond1, *p_cskip, *p_h, *p_t, *p_skip, *p_x, *p_noise;
    cudaGetSymbolAddress((void**)&p_cond1, g_cond1);
    cudaGetSymbolAddress((void**)&p_cskip, g_cskip);
    cudaGetSymbolAddress((void**)&p_h,     g_h);
    cudaGetSymbolAddress((void**)&p_t,     g_t);
    cudaGetSymbolAddress((void**)&p_skip,  g_skip);
    cudaGetSymbolAddress((void**)&p_x,     g_x);
    cudaGetSymbolAddress((void**)&p_noise, g_noise);

    // betas / alphas_cumprod (fp32 sequential cumprod, matching jnp)
    float betas[100], acps[100];
    float cp = 1.0f;
    for (int i = 0; i < 100; i++) {
        betas[i] = (float)(1e-4 + (0.02 - 1e-4) * ((double)i / 99.0));
        cp *= (1.0f - betas[i]);
        acps[i] = cp;
    }

    // PRNG keys: key(42) = [0,42]; fold_in(key,d) = threefry(key; 0, d)
    unsigned kx0, kx1, kn0, kn1;
    threefry2x32(0u, 42u, 0u, 999u, kx0, kx1);
    threefry2x32(0u, 42u, 0u, 7u,   kn0, kn1);

    rng_normal_kernel<<<512, 256>>>(p_x, BSZ * ADIM, kx0, kx1);
    rng_normal_kernel<<<5120, 256>>>(p_noise, INF_STEPS * BSZ * ADIM, kn0, kn1);

    temb_kernel<<<INF_STEPS, 256>>>(time_w, time_b, blk0_w1, blk0_skip_w);

    dim3 ggrid(2, BSZ / GBM);

    sgemm_kernel<1><<<ggrid, 256>>>(features, cond_w, cond_b, nullptr, p_h);
    sgemm_kernel<1><<<ggrid, 256>>>(p_h, blk0_w1, blk0_b1, nullptr, p_cond1);
    sgemm_kernel<1><<<ggrid, 256>>>(p_h, blk0_skip_w, blk0_skip_b, nullptr, p_cskip);

    for (int s = 0; s < INF_STEPS; s++) {
        int t = 90 - 10 * s;
        float b   = betas[t];
        float a   = 1.0f - b;
        float acp = acps[t];
        float c1  = b / sqrtf(1.0f - acp);
        float sa  = sqrtf(a);
        float sb  = sqrtf(b);

        build_kernel<<<BSZ, 256>>>(blk0_w1, blk0_skip_w, s);

        sgemm_kernel<7><<<ggrid, 256>>>(p_t, blk0_w2, blk0_b2, p_skip, p_h);

        for (int i = 0; i < 3; i++) {
            sgemm_kernel<3><<<ggrid, 256>>>(p_h, blks_w1 + i * 65536,
                                            blks_b1 + i * 256, nullptr, p_t);
            sgemm_kernel<7><<<ggrid, 256>>>(p_t, blks_w2 + i * 65536,
                                            blks_b2 + i * 256, p_h, p_h);
        }

        final_update_kernel<<<BSZ / 64, 256>>>(final_w, final_b, s, c1, sa, sb,
                                               (t > 0) ? 1 : 0,
                                               (s == INF_STEPS - 1) ? (float*)d_out
                                                                    : nullptr);
    }
}